// round 13
// baseline (speedup 1.0000x reference)
#include <cuda_runtime.h>
#include <cstdint>

// KerasArima: y_t = ca*x_t + cb*x_{t-1} + th1*y_{t-1} + th2*y_{t-2}
//   ca = 1 + phi - th1,  cb = -phi - th2
//
// x (B=64, T=2048, HW=256) f32. CHUNK=128 time-chunks, WARM=8 warm-up.
//
// R13: 256-bit memory ops (sm_10x LDG.256/STG.256 via .v8.b32). Each thread
// owns 8 consecutive floats (32B); a 32-thread warp moves 1KB/instruction.
// Halves LDG/STG instruction count and L1 wavefronts per byte vs float4.
// UN=4 timestep groups keep 128B/thread in flight. CTA = 32 threads,
// grid = 1024 -> 6.92 CTAs/SM balanced single wave (same as best R8).
// Stores are .cs (evict-first streaming). L2 policy hints: tested R11/R12,
// null -> plain loads.

#define HWL   32             // 256 floats / 8 per thread
#define ROW   256            // floats per timestep row
#define TT    2048
#define CHUNK 128
#define WARM  8
#define NC    (TT / CHUNK)   // 16 chunks
#define UN    4              // timesteps per group
#define BLK   32

__device__ __forceinline__ void ld256(const float* p, float v[8]) {
    uint32_t r0, r1, r2, r3, r4, r5, r6, r7;
    asm volatile("ld.global.v8.b32 {%0,%1,%2,%3,%4,%5,%6,%7}, [%8];"
                 : "=r"(r0), "=r"(r1), "=r"(r2), "=r"(r3),
                   "=r"(r4), "=r"(r5), "=r"(r6), "=r"(r7)
                 : "l"(p));
    v[0] = __uint_as_float(r0); v[1] = __uint_as_float(r1);
    v[2] = __uint_as_float(r2); v[3] = __uint_as_float(r3);
    v[4] = __uint_as_float(r4); v[5] = __uint_as_float(r5);
    v[6] = __uint_as_float(r6); v[7] = __uint_as_float(r7);
}

__device__ __forceinline__ void st256cs(float* p, const float v[8]) {
    asm volatile("st.global.cs.v8.b32 [%0], {%1,%2,%3,%4,%5,%6,%7,%8};"
                 :: "l"(p),
                    "r"(__float_as_uint(v[0])), "r"(__float_as_uint(v[1])),
                    "r"(__float_as_uint(v[2])), "r"(__float_as_uint(v[3])),
                    "r"(__float_as_uint(v[4])), "r"(__float_as_uint(v[5])),
                    "r"(__float_as_uint(v[6])), "r"(__float_as_uint(v[7]))
                 : "memory");
}

__global__ void __launch_bounds__(BLK, 14) arima_kernel(
    const float* __restrict__ x, float* __restrict__ y,
    const float* __restrict__ phi_p, const float* __restrict__ th1_p,
    const float* __restrict__ th2_p, const float* __restrict__ e0_p)
{
    const float phi = __ldg(phi_p);
    const float th1 = __ldg(th1_p);
    const float th2 = __ldg(th2_p);
    const float e0  = __ldg(e0_p);
    const float ca  = 1.0f + phi - th1;
    const float cb  = -phi - th2;

    const int g    = blockIdx.x * BLK + threadIdx.x;
    const int lane = g & (HWL - 1);        // 8-float lane within the row
    const int c    = (g >> 5) & (NC - 1);  // time chunk (uniform per CTA)
    const int b    = g >> 9;               // batch

    const float* xr = x + (size_t)b * TT * ROW + lane * 8;
    float*       yr = y + (size_t)b * TT * ROW + lane * 8;

    const int s = c * CHUNK;               // first stored timestep
    float ym1[8], ym2[8], xm[8];

    const float* xp;
    float*       yp;

    if (c == 0) {
        // Exact initial conditions for t=0,1, then t=2,3 head (so the main
        // loop runs 31 uniform groups of 4 covering t=4..127).
        float x0[8], x1[8];
        ld256(xr,       x0);
        ld256(xr + ROW, x1);
        float y0[8], y1[8];
        #pragma unroll
        for (int i = 0; i < 8; i++) y0[i] = x0[i] - th1 * e0;
        #pragma unroll
        for (int i = 0; i < 8; i++)
            y1[i] = x1[i] + phi * (x1[i] - x0[i]) - th1 * (x1[i] - y0[i]) - th2 * e0;
        st256cs(yr,       y0);
        st256cs(yr + ROW, y1);
        #pragma unroll
        for (int i = 0; i < 8; i++) { ym2[i] = y0[i]; ym1[i] = y1[i]; xm[i] = x1[i]; }

        // t = 2, 3
        #pragma unroll
        for (int t = 2; t < 4; t++) {
            float xv[8], yt[8];
            ld256(xr + (size_t)t * ROW, xv);
            #pragma unroll
            for (int i = 0; i < 8; i++)
                yt[i] = ca * xv[i] + cb * xm[i] + th1 * ym1[i] + th2 * ym2[i];
            st256cs(yr + (size_t)t * ROW, yt);
            #pragma unroll
            for (int i = 0; i < 8; i++) { ym2[i] = ym1[i]; ym1[i] = yt[i]; xm[i] = xv[i]; }
        }
        xp = xr + (size_t)4 * ROW;
        yp = yr + (size_t)4 * ROW;

        // 31 groups of 4 (t=4..127)
        #pragma unroll 1
        for (int gi = 0; gi < 31; gi++, xp += UN * ROW, yp += UN * ROW) {
            float xv[UN][8];
            #pragma unroll
            for (int k = 0; k < UN; k++) ld256(xp + (size_t)k * ROW, xv[k]);
            #pragma unroll
            for (int k = 0; k < UN; k++) {
                float yt[8];
                #pragma unroll
                for (int i = 0; i < 8; i++)
                    yt[i] = ca * xv[k][i] + cb * xm[i] + th1 * ym1[i] + th2 * ym2[i];
                st256cs(yp + (size_t)k * ROW, yt);
                #pragma unroll
                for (int i = 0; i < 8; i++) { ym2[i] = ym1[i]; ym1[i] = yt[i]; xm[i] = xv[k][i]; }
            }
        }
    } else {
        // Warm-up seed y ~= x, two steps before the warm window.
        const int t0 = s - WARM;            // >= 120, safe
        {
            float xa[8], xb[8];
            ld256(xr + (size_t)(t0 - 2) * ROW, xa);
            ld256(xr + (size_t)(t0 - 1) * ROW, xb);
            #pragma unroll
            for (int i = 0; i < 8; i++) { ym2[i] = xa[i]; ym1[i] = xb[i]; xm[i] = xb[i]; }
        }
        xp = xr + (size_t)t0 * ROW;
        yp = yr + (size_t)s * ROW;

        // Warm-up: 2 groups of 4, no stores.
        #pragma unroll 1
        for (int gw = 0; gw < WARM / UN; gw++, xp += UN * ROW) {
            float xv[UN][8];
            #pragma unroll
            for (int k = 0; k < UN; k++) ld256(xp + (size_t)k * ROW, xv[k]);
            #pragma unroll
            for (int k = 0; k < UN; k++) {
                float yt[8];
                #pragma unroll
                for (int i = 0; i < 8; i++)
                    yt[i] = ca * xv[k][i] + cb * xm[i] + th1 * ym1[i] + th2 * ym2[i];
                #pragma unroll
                for (int i = 0; i < 8; i++) { ym2[i] = ym1[i]; ym1[i] = yt[i]; xm[i] = xv[k][i]; }
            }
        }

        // Stored region: 32 groups of 4, streaming 256-bit stores.
        #pragma unroll 1
        for (int gi = 0; gi < CHUNK / UN; gi++, xp += UN * ROW, yp += UN * ROW) {
            float xv[UN][8];
            #pragma unroll
            for (int k = 0; k < UN; k++) ld256(xp + (size_t)k * ROW, xv[k]);
            #pragma unroll
            for (int k = 0; k < UN; k++) {
                float yt[8];
                #pragma unroll
                for (int i = 0; i < 8; i++)
                    yt[i] = ca * xv[k][i] + cb * xm[i] + th1 * ym1[i] + th2 * ym2[i];
                st256cs(yp + (size_t)k * ROW, yt);
                #pragma unroll
                for (int i = 0; i < 8; i++) { ym2[i] = ym1[i]; ym1[i] = yt[i]; xm[i] = xv[k][i]; }
            }
        }
    }
}

extern "C" void kernel_launch(void* const* d_in, const int* in_sizes, int n_in,
                              void* d_out, int out_size)
{
    const float* x   = (const float*)d_in[0];
    const float* phi = (const float*)d_in[1];
    const float* th1 = (const float*)d_in[2];
    const float* th2 = (const float*)d_in[3];
    const float* e0  = (const float*)d_in[4];
    float*       y   = (float*)d_out;

    // threads = B * NC * HWL = 64 * 16 * 32 = 32768 -> 1024 blocks x 32
    arima_kernel<<<1024, BLK>>>(x, y, phi, th1, th2, e0);
}

// round 14
// speedup vs baseline: 1.0359x; 1.0359x over previous
#include <cuda_runtime.h>

// KerasArima: y_t = ca*x_t + cb*x_{t-1} + th1*y_{t-1} + th2*y_{t-2}
//   ca = 1 + phi - th1,  cb = -phi - th2
//
// x (B=64, T=2048, HW=256) f32. CHUNK=128 time-chunks, WARM=8 warm-up.
//
// R14: max-warp variant. Each thread owns 2 floats (float2), 128 lanes/row
// -> 131072 threads, 2048 CTAs x 64 -> 13.84 CTAs/SM, busiest SM 896
// threads (balance 1.011). Same obligatory traffic as R8 (~264 MiB) and
// same per-SM bytes-in-flight (UN=8 x 8B x 896 thr), but 2x the warps to
// interleave loads across FMA-chain gaps. R13 showed fewer warps hurt;
// this tests whether more warps help at the same traffic.
// __ldcs evict-first reads (read-once), __stcs evict-first writes
// (write-once); L2 policy pinning tested R11/R12 -> null.

#define HWL   128            // 256 floats / 2 per thread
#define TT    2048
#define CHUNK 128
#define WARM  8
#define NC    (TT / CHUNK)   // 16 chunks
#define UN    8              // prefetch unroll
#define BLK   64

__device__ __forceinline__ float2 arima_step2(
    const float2 xv, const float2 xm, const float2 ym1, const float2 ym2,
    const float ca, const float cb, const float th1, const float th2)
{
    float2 yt;
    yt.x = ca * xv.x + cb * xm.x + th1 * ym1.x + th2 * ym2.x;
    yt.y = ca * xv.y + cb * xm.y + th1 * ym1.y + th2 * ym2.y;
    return yt;
}

__global__ void __launch_bounds__(BLK, 14) arima_kernel(
    const float2* __restrict__ x, float2* __restrict__ y,
    const float* __restrict__ phi_p, const float* __restrict__ th1_p,
    const float* __restrict__ th2_p, const float* __restrict__ e0_p)
{
    const float phi = __ldg(phi_p);
    const float th1 = __ldg(th1_p);
    const float th2 = __ldg(th2_p);
    const float e0  = __ldg(e0_p);
    const float ca  = 1.0f + phi - th1;
    const float cb  = -phi - th2;

    const int g    = blockIdx.x * BLK + threadIdx.x;
    const int lane = g & (HWL - 1);        // float2 index within 256-wide row
    const int c    = (g >> 7) & (NC - 1);  // time chunk
    const int b    = g >> 11;              // batch (64*16*128 threads total)

    const float2* xr = x + (size_t)b * TT * HWL + lane;
    float2*       yr = y + (size_t)b * TT * HWL + lane;

    const int s = c * CHUNK;               // first stored timestep
    float2 ym1, ym2, xm;

    if (c == 0) {
        // Exact initial conditions, then 126 stored steps.
        float2 x0 = __ldcs(&xr[0]);
        float2 x1 = __ldcs(&xr[HWL]);
        float2 y0, y1;
        y0.x = x0.x - th1 * e0;
        y0.y = x0.y - th1 * e0;
        y1.x = x1.x + phi * (x1.x - x0.x) - th1 * (x1.x - y0.x) - th2 * e0;
        y1.y = x1.y + phi * (x1.y - x0.y) - th1 * (x1.y - y0.y) - th2 * e0;
        __stcs(&yr[0],   y0);
        __stcs(&yr[HWL], y1);
        ym2 = y0; ym1 = y1; xm = x1;

        const float2* xp = xr + (size_t)2 * HWL;
        float2*       yp = yr + (size_t)2 * HWL;
        // 15 groups of 8 (t=2..121)
        #pragma unroll 1
        for (int gi = 0; gi < 15; gi++, xp += UN * HWL, yp += UN * HWL) {
            float2 xv[UN];
            #pragma unroll
            for (int k = 0; k < UN; k++) xv[k] = __ldcs(&xp[k * HWL]);
            #pragma unroll
            for (int k = 0; k < UN; k++) {
                float2 yt = arima_step2(xv[k], xm, ym1, ym2, ca, cb, th1, th2);
                __stcs(&yp[k * HWL], yt);
                ym2 = ym1; ym1 = yt; xm = xv[k];
            }
        }
        // remainder: 6 steps (t=122..127)
        #pragma unroll
        for (int k = 0; k < 6; k++) {
            float2 xv = __ldcs(&xp[k * HWL]);
            float2 yt = arima_step2(xv, xm, ym1, ym2, ca, cb, th1, th2);
            __stcs(&yp[k * HWL], yt);
            ym2 = ym1; ym1 = yt; xm = xv;
        }
    } else {
        // Warm-up seed y ~= x, two steps before the warm window.
        const int t0 = s - WARM;            // >= 120, safe
        {
            float2 xa = __ldcs(&xr[(size_t)(t0 - 2) * HWL]);
            float2 xb = __ldcs(&xr[(size_t)(t0 - 1) * HWL]);
            ym2 = xa; ym1 = xb; xm = xb;
        }
        const float2* xp = xr + (size_t)t0 * HWL;
        float2*       yp = yr + (size_t)s * HWL;

        // Warm-up: one group of 8, no stores.
        {
            float2 xv[UN];
            #pragma unroll
            for (int k = 0; k < UN; k++) xv[k] = __ldcs(&xp[k * HWL]);
            xp += UN * HWL;
            #pragma unroll
            for (int k = 0; k < UN; k++) {
                float2 yt = arima_step2(xv[k], xm, ym1, ym2, ca, cb, th1, th2);
                ym2 = ym1; ym1 = yt; xm = xv[k];
            }
        }
        // Stored region: 16 groups of 8, streaming stores.
        #pragma unroll 1
        for (int gi = 0; gi < CHUNK / UN; gi++, xp += UN * HWL, yp += UN * HWL) {
            float2 xv[UN];
            #pragma unroll
            for (int k = 0; k < UN; k++) xv[k] = __ldcs(&xp[k * HWL]);
            #pragma unroll
            for (int k = 0; k < UN; k++) {
                float2 yt = arima_step2(xv[k], xm, ym1, ym2, ca, cb, th1, th2);
                __stcs(&yp[k * HWL], yt);
                ym2 = ym1; ym1 = yt; xm = xv[k];
            }
        }
    }
}

extern "C" void kernel_launch(void* const* d_in, const int* in_sizes, int n_in,
                              void* d_out, int out_size)
{
    const float2* x   = (const float2*)d_in[0];
    const float*  phi = (const float*)d_in[1];
    const float*  th1 = (const float*)d_in[2];
    const float*  th2 = (const float*)d_in[3];
    const float*  e0  = (const float*)d_in[4];
    float2*       y   = (float2*)d_out;

    // threads = B * NC * HWL = 64 * 16 * 128 = 131072 -> 2048 blocks x 64
    arima_kernel<<<2048, BLK>>>(x, y, phi, th1, th2, e0);
}